// round 8
// baseline (speedup 1.0000x reference)
// SCNNModel — fp32x2 v5: 2-CTA/SM nonlin (slim smem), prefetching 8-wide sconv.
#include <cuda_runtime.h>
#include <math.h>
#include <stdint.h>

#define BATCH 16384
#define PI_F 3.14159265358979323846f
typedef unsigned long long u64;

__device__ float g_x48[BATCH * 4   * 48];
__device__ float g_yb [BATCH * 128 * 48];
__device__ float g_e1 [BATCH * 16  * 48];
__device__ float g_e2 [BATCH * 32  * 48];
__device__ float g_e3 [BATCH * 64  * 48];
__device__ float g_e4 [BATCH * 128 * 48];
__device__ float g_d1 [BATCH * 128 * 48];
__device__ float g_d2 [BATCH * 64  * 48];
__device__ float g_d3 [BATCH * 32  * 48];
__device__ float g_d4 [BATCH * 16  * 48];

__device__ __forceinline__ u64 pack2(float x, float y) {
    u64 r;
    asm("mov.b64 %0, {%1, %2};" : "=l"(r) : "f"(x), "f"(y));
    return r;
}
__device__ __forceinline__ void unpack2(u64 v, float& x, float& y) {
    asm("mov.b64 {%0, %1}, %2;" : "=f"(x), "=f"(y) : "l"(v));
}
__device__ __forceinline__ void fma2(u64& d, u64 a, u64 b) {
    asm("fma.rn.f32x2 %0, %1, %2, %0;" : "+l"(d) : "l"(a), "l"(b));
}
__device__ __forceinline__ int lh_of(int c) {
    return (c < 1) ? 0 : (c < 6) ? 1 : (c < 15) ? 2 : (c < 28) ? 3 : 4;
}

__global__ void pad48(const float* __restrict__ x, float* __restrict__ xp)
{
    int idx = blockIdx.x * blockDim.x + threadIdx.x;
    if (idx >= BATCH * 4 * 48) return;
    int c = idx % 48;
    xp[idx] = (c < 45) ? x[(idx / 48) * 45 + c] : 0.f;
}

// ---------------- sconv v5 ----------------
template<int I, int O>
__global__ void __launch_bounds__(192, 3)
sconv5(const float* __restrict__ x, const float* __restrict__ w,
       float* __restrict__ y)
{
    constexpr int OCTA = (O >= 64) ? 64 : O;
    constexpr int OGO  = OCTA / 8;                    // 8 / 4 / 2
    constexpr int NB   = (OGO == 2) ? 8 : 4;
    constexpr int IH   = (I < 32) ? I : 32;
    __shared__ float w5s[OCTA * IH * 5];

    const int tid = threadIdx.x;
    const int cp  = tid % 24;
    const int og  = tid / 24;
    const int b0  = blockIdx.x * NB;
    const int o0g = blockIdx.y * OCTA;
    const int c0  = 2 * cp;
    const int lh0 = lh_of(c0), lh1 = lh_of(c0 + 1);

    u64 acc[NB][OGO];
    #pragma unroll
    for (int b = 0; b < NB; b++)
        #pragma unroll
        for (int j = 0; j < OGO; j++) acc[b][j] = 0ull;

    for (int ih0 = 0; ih0 < I; ih0 += IH) {
        __syncthreads();
        for (int idx = tid; idx < OCTA * IH * 5; idx += 192) {
            int lh  = idx % 5;
            int rem = idx / 5;
            int ii  = rem % IH, o = rem / IH;
            float lf = sqrtf(PI_F / (4.f * (float)lh + 1.f));
            w5s[(o * IH + ii) * 5 + lh] =
                w[((size_t)(o0g + o) * I + ih0 + ii) * 5 + lh] * lf;
        }
        __syncthreads();

        u64 xa[NB], xb[NB];
        #pragma unroll
        for (int b = 0; b < NB; b++)
            xa[b] = *(const u64*)(x + ((size_t)(b0 + b) * I + ih0) * 48 + c0);

        #pragma unroll
        for (int ii = 0; ii < IH; ii += 2) {
            if (ii + 1 < IH) {
                #pragma unroll
                for (int b = 0; b < NB; b++)
                    xb[b] = *(const u64*)(x + ((size_t)(b0 + b) * I + ih0 + ii + 1) * 48 + c0);
            }
            {   // compute ii with xa
                u64 wv[OGO];
                #pragma unroll
                for (int j = 0; j < OGO; j++) {
                    const float* wp = w5s + ((og * OGO + j) * IH + ii) * 5;
                    wv[j] = pack2(wp[lh0], wp[lh1]);
                }
                #pragma unroll
                for (int b = 0; b < NB; b++)
                    #pragma unroll
                    for (int j = 0; j < OGO; j++) fma2(acc[b][j], xa[b], wv[j]);
            }
            if (ii + 1 < IH) {
                if (ii + 2 < IH) {
                    #pragma unroll
                    for (int b = 0; b < NB; b++)
                        xa[b] = *(const u64*)(x + ((size_t)(b0 + b) * I + ih0 + ii + 2) * 48 + c0);
                }
                u64 wv[OGO];
                #pragma unroll
                for (int j = 0; j < OGO; j++) {
                    const float* wp = w5s + ((og * OGO + j) * IH + ii + 1) * 5;
                    wv[j] = pack2(wp[lh0], wp[lh1]);
                }
                #pragma unroll
                for (int b = 0; b < NB; b++)
                    #pragma unroll
                    for (int j = 0; j < OGO; j++) fma2(acc[b][j], xb[b], wv[j]);
            }
        }
    }
    #pragma unroll
    for (int b = 0; b < NB; b++)
        #pragma unroll
        for (int j = 0; j < OGO; j++)
            *(u64*)(y + ((size_t)(b0 + b) * O + o0g + og * OGO + j) * 48 + c0) = acc[b][j];
}

// ---------------- nonlin v5: 128-row tiles, 2 CTAs/SM ----------------
// smem: bi2 u64[45][56] | bs2 u64[100][24] | ysT f[45][129] | tsT f[100][128] (outs overlay [128][49])
#define NL_SMEM (20160 + 19200 + 23220 + 51200)

template<int OO, int O, int OS>
__global__ void __launch_bounds__(512, 2)
nonlin5(const float* __restrict__ y, const float* __restrict__ skip,
        const float* __restrict__ isft, const float* __restrict__ sft,
        float* __restrict__ out)
{
    extern __shared__ char smraw[];
    u64*   bi2 = (u64*)smraw;                  // [45][56]
    u64*   bs2 = bi2 + 45 * 56;                // [100][24]
    float* ysT = (float*)(bs2 + 100 * 24);     // [45][129]
    float* tsT = ysT + 45 * 129;               // [100][128]

    const int tid = threadIdx.x;
    const int w   = tid >> 5;
    const int rg  = tid & 31;
    const int rr0 = rg + (w & 1) * 32;         // rows rr0, rr0+64
    const int blk = w >> 1;                    // 0..7

    for (int idx = tid; idx < 45 * 56; idx += 512) {
        int k = idx / 56, dp = idx % 56;
        float a = (2 * dp     < 100) ? isft[(2 * dp) * 45 + k]     : 0.f;
        float b = (2 * dp + 1 < 100) ? isft[(2 * dp + 1) * 45 + k] : 0.f;
        bi2[idx] = pack2(a, b);
    }
    for (int idx = tid; idx < 100 * 24; idx += 512) {
        int d = idx / 24, cq = idx % 24;
        float a = (2 * cq     < 45) ? sft[(2 * cq) * 100 + d]     : 0.f;
        float b = (2 * cq + 1 < 45) ? sft[(2 * cq + 1) * 100 + d] : 0.f;
        bs2[idx] = pack2(a, b);
    }
    __syncthreads();

    const int NT = (BATCH * OO) / 128;
    for (int tile = blockIdx.x; tile < NT; tile += gridDim.x) {
        for (int idx = tid; idx < 128 * 48; idx += 512) {
            int r = idx / 48, c = idx % 48;
            if (c < 45) {
                int gr = tile * 128 + r;
                int b = gr / OO, oo = gr % OO;
                float v;
                if (OS == 0 || oo < O) v = y[((size_t)b * O + oo) * 48 + c];
                else                   v = skip[((size_t)b * OS + (oo - O)) * 48 + c];
                ysT[c * 129 + r] = v;
            }
        }
        __syncthreads();

        // GEMM1: 2 rows x 7 d-pairs
        {
            u64 acc[2][7];
            #pragma unroll
            for (int j = 0; j < 2; j++)
                #pragma unroll
                for (int q = 0; q < 7; q++) acc[j][q] = 0ull;
            #pragma unroll 5
            for (int k = 0; k < 45; k++) {
                float v0 = ysT[k * 129 + rr0];
                float v1 = ysT[k * 129 + rr0 + 64];
                u64 a0 = pack2(v0, v0), a1 = pack2(v1, v1);
                #pragma unroll
                for (int q = 0; q < 7; q++) {
                    u64 bv = bi2[k * 56 + blk * 7 + q];
                    fma2(acc[0][q], a0, bv);
                    fma2(acc[1][q], a1, bv);
                }
            }
            #pragma unroll
            for (int q = 0; q < 7; q++) {
                int d = 2 * (blk * 7 + q);
                #pragma unroll
                for (int j = 0; j < 2; j++) {
                    float lo, hi;
                    unpack2(acc[j][q], lo, hi);
                    int r = rr0 + 64 * j;
                    if (d < 100)     tsT[d * 128 + r]       = fmaxf(lo, 0.f);
                    if (d + 1 < 100) tsT[(d + 1) * 128 + r] = fmaxf(hi, 0.f);
                }
            }
        }
        __syncthreads();

        // GEMM2: 2 rows x 3 c-pairs
        u64 acc2[2][3];
        #pragma unroll
        for (int j = 0; j < 2; j++)
            #pragma unroll
            for (int q = 0; q < 3; q++) acc2[j][q] = 0ull;
        #pragma unroll 5
        for (int k = 0; k < 100; k++) {
            float v0 = tsT[k * 128 + rr0];
            float v1 = tsT[k * 128 + rr0 + 64];
            u64 a0 = pack2(v0, v0), a1 = pack2(v1, v1);
            #pragma unroll
            for (int q = 0; q < 3; q++) {
                u64 bv = bs2[k * 24 + blk * 3 + q];
                fma2(acc2[0][q], a0, bv);
                fma2(acc2[1][q], a1, bv);
            }
        }
        __syncthreads();                       // tsT reads done; overlay outs
        {
            float* outs = tsT;                 // [128][49]
            #pragma unroll
            for (int q = 0; q < 3; q++) {
                int c = 2 * (blk * 3 + q);
                #pragma unroll
                for (int j = 0; j < 2; j++) {
                    float lo, hi;
                    unpack2(acc2[j][q], lo, hi);
                    int r = rr0 + 64 * j;
                    outs[r * 49 + c]     = lo;
                    outs[r * 49 + c + 1] = hi;
                }
            }
        }
        __syncthreads();
        {
            const float* outs = tsT;
            size_t base = (size_t)tile * 128 * 48;
            for (int idx = tid; idx < 128 * 48; idx += 512)
                out[base + idx] = outs[(idx / 48) * 49 + idx % 48];
        }
        __syncthreads();
    }
}

__global__ void final_sconv(const float* __restrict__ d4,
                            const float* __restrict__ w9,
                            float* __restrict__ out)
{
    __shared__ float ws[80];
    int tid = threadIdx.x;
    if (tid < 80) {
        int lh = tid % 5;
        ws[tid] = w9[tid] * sqrtf(PI_F / (4.f * (float)lh + 1.f));
    }
    __syncthreads();
    int idx = blockIdx.x * blockDim.x + tid;
    if (idx >= BATCH * 45) return;
    int c = idx % 45;
    int b = idx / 45;
    int lh = lh_of(c);
    float acc = 0.f;
    #pragma unroll
    for (int i = 0; i < 16; i++)
        acc += d4[((size_t)b * 16 + i) * 48 + c] * ws[i * 5 + lh];
    out[idx] = acc;
}

template<int I, int O>
static void run_sconv(const float* in, const float* w, float* y)
{
    constexpr int OCTA = (O >= 64) ? 64 : O;
    constexpr int OGO  = OCTA / 8;
    constexpr int NB   = (OGO == 2) ? 8 : 4;
    dim3 grid(BATCH / NB, O / OCTA);
    sconv5<I, O><<<grid, 192>>>(in, w, y);
}

template<int OO, int O, int OS>
static void run_nonlin(const float* y, const float* skip,
                       const float* isft, const float* sft, float* out)
{
    auto kf = nonlin5<OO, O, OS>;
    cudaFuncSetAttribute(kf, cudaFuncAttributeMaxDynamicSharedMemorySize, NL_SMEM);
    kf<<<296, 512, NL_SMEM>>>(y, skip, isft, sft, out);
}

extern "C" void kernel_launch(void* const* d_in, const int* in_sizes, int n_in,
                              void* d_out, int out_size)
{
    const float* x    = (const float*)d_in[0];
    const float* sft  = (const float*)d_in[1];
    const float* isft = (const float*)d_in[2];
    const float* w[9];
    for (int k = 0; k < 9; k++) w[k] = (const float*)d_in[3 + k];
    float* out = (float*)d_out;

    float *x48, *yb, *e1, *e2, *e3, *e4, *d1, *d2, *d3, *d4;
    cudaGetSymbolAddress((void**)&x48, g_x48);
    cudaGetSymbolAddress((void**)&yb, g_yb);
    cudaGetSymbolAddress((void**)&e1, g_e1);
    cudaGetSymbolAddress((void**)&e2, g_e2);
    cudaGetSymbolAddress((void**)&e3, g_e3);
    cudaGetSymbolAddress((void**)&e4, g_e4);
    cudaGetSymbolAddress((void**)&d1, g_d1);
    cudaGetSymbolAddress((void**)&d2, g_d2);
    cudaGetSymbolAddress((void**)&d3, g_d3);
    cudaGetSymbolAddress((void**)&d4, g_d4);

    pad48<<<(BATCH * 4 * 48 + 255) / 256, 256>>>(x, x48);

    run_sconv<4, 16>(x48, w[0], yb);
    run_nonlin<16, 16, 0>(yb, yb, isft, sft, e1);

    run_sconv<16, 32>(e1, w[1], yb);
    run_nonlin<32, 32, 0>(yb, yb, isft, sft, e2);

    run_sconv<32, 64>(e2, w[2], yb);
    run_nonlin<64, 64, 0>(yb, yb, isft, sft, e3);

    run_sconv<64, 128>(e3, w[3], yb);
    run_nonlin<128, 128, 0>(yb, yb, isft, sft, e4);

    run_sconv<128, 64>(e4, w[4], yb);
    run_nonlin<128, 64, 64>(yb, e3, isft, sft, d1);

    run_sconv<128, 32>(d1, w[5], yb);
    run_nonlin<64, 32, 32>(yb, e2, isft, sft, d2);

    run_sconv<64, 16>(d2, w[6], yb);
    run_nonlin<32, 16, 16>(yb, e1, isft, sft, d3);

    run_sconv<32, 16>(d3, w[7], yb);
    run_nonlin<16, 16, 0>(yb, yb, isft, sft, d4);

    final_sconv<<<(BATCH * 45 + 255) / 256, 256>>>(d4, w[8], out);
}

// round 10
// speedup vs baseline: 1.0343x; 1.0343x over previous
// SCNNModel — fp32x2 v6b: nonlin cp.async double-buffered staging (FIXED:
// 12 x 16B chunks per 48-float row), 192-row tiles; sconv5 kept.
#include <cuda_runtime.h>
#include <math.h>
#include <stdint.h>

#define BATCH 16384
#define PI_F 3.14159265358979323846f
typedef unsigned long long u64;

__device__ float g_x48[BATCH * 4   * 48];
__device__ float g_yb [BATCH * 128 * 48];
__device__ float g_e1 [BATCH * 16  * 48];
__device__ float g_e2 [BATCH * 32  * 48];
__device__ float g_e3 [BATCH * 64  * 48];
__device__ float g_e4 [BATCH * 128 * 48];
__device__ float g_d1 [BATCH * 128 * 48];
__device__ float g_d2 [BATCH * 64  * 48];
__device__ float g_d3 [BATCH * 32  * 48];
__device__ float g_d4 [BATCH * 16  * 48];

__device__ __forceinline__ u64 pack2(float x, float y) {
    u64 r;
    asm("mov.b64 %0, {%1, %2};" : "=l"(r) : "f"(x), "f"(y));
    return r;
}
__device__ __forceinline__ void unpack2(u64 v, float& x, float& y) {
    asm("mov.b64 {%0, %1}, %2;" : "=f"(x), "=f"(y) : "l"(v));
}
__device__ __forceinline__ void fma2(u64& d, u64 a, u64 b) {
    asm("fma.rn.f32x2 %0, %1, %2, %0;" : "+l"(d) : "l"(a), "l"(b));
}
__device__ __forceinline__ int lh_of(int c) {
    return (c < 1) ? 0 : (c < 6) ? 1 : (c < 15) ? 2 : (c < 28) ? 3 : 4;
}
__device__ __forceinline__ uint32_t smem_u32(const void* p) {
    uint32_t a;
    asm("{ .reg .u64 t; cvta.to.shared.u64 t, %1; cvt.u32.u64 %0, t; }"
        : "=r"(a) : "l"(p));
    return a;
}
__device__ __forceinline__ void cp_async16(uint32_t dst, const void* src) {
    asm volatile("cp.async.cg.shared.global [%0], [%1], 16;" :: "r"(dst), "l"(src));
}
#define CP_COMMIT() asm volatile("cp.async.commit_group;")
#define CP_WAIT0()  asm volatile("cp.async.wait_group 0;")

__global__ void pad48(const float* __restrict__ x, float* __restrict__ xp)
{
    int idx = blockIdx.x * blockDim.x + threadIdx.x;
    if (idx >= BATCH * 4 * 48) return;
    int c = idx % 48;
    xp[idx] = (c < 45) ? x[(idx / 48) * 45 + c] : 0.f;
}

// ---------------- sconv v5 (best measured; unchanged) ----------------
template<int I, int O>
__global__ void __launch_bounds__(192, 3)
sconv5(const float* __restrict__ x, const float* __restrict__ w,
       float* __restrict__ y)
{
    constexpr int OCTA = (O >= 64) ? 64 : O;
    constexpr int OGO  = OCTA / 8;
    constexpr int NB   = (OGO == 2) ? 8 : 4;
    constexpr int IH   = (I < 32) ? I : 32;
    __shared__ float w5s[OCTA * IH * 5];

    const int tid = threadIdx.x;
    const int cp  = tid % 24;
    const int og  = tid / 24;
    const int b0  = blockIdx.x * NB;
    const int o0g = blockIdx.y * OCTA;
    const int c0  = 2 * cp;
    const int lh0 = lh_of(c0), lh1 = lh_of(c0 + 1);

    u64 acc[NB][OGO];
    #pragma unroll
    for (int b = 0; b < NB; b++)
        #pragma unroll
        for (int j = 0; j < OGO; j++) acc[b][j] = 0ull;

    for (int ih0 = 0; ih0 < I; ih0 += IH) {
        __syncthreads();
        for (int idx = tid; idx < OCTA * IH * 5; idx += 192) {
            int lh  = idx % 5;
            int rem = idx / 5;
            int ii  = rem % IH, o = rem / IH;
            float lf = sqrtf(PI_F / (4.f * (float)lh + 1.f));
            w5s[(o * IH + ii) * 5 + lh] =
                w[((size_t)(o0g + o) * I + ih0 + ii) * 5 + lh] * lf;
        }
        __syncthreads();

        u64 xa[NB], xb[NB];
        #pragma unroll
        for (int b = 0; b < NB; b++)
            xa[b] = *(const u64*)(x + ((size_t)(b0 + b) * I + ih0) * 48 + c0);

        #pragma unroll
        for (int ii = 0; ii < IH; ii += 2) {
            if (ii + 1 < IH) {
                #pragma unroll
                for (int b = 0; b < NB; b++)
                    xb[b] = *(const u64*)(x + ((size_t)(b0 + b) * I + ih0 + ii + 1) * 48 + c0);
            }
            {
                u64 wv[OGO];
                #pragma unroll
                for (int j = 0; j < OGO; j++) {
                    const float* wp = w5s + ((og * OGO + j) * IH + ii) * 5;
                    wv[j] = pack2(wp[lh0], wp[lh1]);
                }
                #pragma unroll
                for (int b = 0; b < NB; b++)
                    #pragma unroll
                    for (int j = 0; j < OGO; j++) fma2(acc[b][j], xa[b], wv[j]);
            }
            if (ii + 1 < IH) {
                if (ii + 2 < IH) {
                    #pragma unroll
                    for (int b = 0; b < NB; b++)
                        xa[b] = *(const u64*)(x + ((size_t)(b0 + b) * I + ih0 + ii + 2) * 48 + c0);
                }
                u64 wv[OGO];
                #pragma unroll
                for (int j = 0; j < OGO; j++) {
                    const float* wp = w5s + ((og * OGO + j) * IH + ii + 1) * 5;
                    wv[j] = pack2(wp[lh0], wp[lh1]);
                }
                #pragma unroll
                for (int b = 0; b < NB; b++)
                    #pragma unroll
                    for (int j = 0; j < OGO; j++) fma2(acc[b][j], xb[b], wv[j]);
            }
        }
    }
    #pragma unroll
    for (int b = 0; b < NB; b++)
        #pragma unroll
        for (int j = 0; j < OGO; j++)
            *(u64*)(y + ((size_t)(b0 + b) * O + o0g + og * OGO + j) * 48 + c0) = acc[b][j];
}

// ---------------- nonlin v6b ----------------
// smem: bi2 u64[45][56] | bs2 u64[100][24] | ys0 f[192][48] | ys1 f[192][48] | ts f[192][104]
#define NL6_SMEM (20160 + 19200 + 36864 + 36864 + 79872)

template<int OO, int O, int OS>
__global__ void __launch_bounds__(512, 1)
nonlin6(const float* __restrict__ y, const float* __restrict__ skip,
        const float* __restrict__ isft, const float* __restrict__ sft,
        float* __restrict__ out)
{
    extern __shared__ char smraw[];
    u64*   bi2 = (u64*)smraw;
    u64*   bs2 = bi2 + 45 * 56;
    float* ys0 = (float*)(bs2 + 100 * 24);
    float* ys1 = ys0 + 192 * 48;
    float* ts  = ys1 + 192 * 48;

    const int tid = threadIdx.x;
    const int rg  = tid >> 3;              // 0..63 (3 rows each)
    const int blk = tid & 7;               // 0..7
    const int r0  = rg * 3;

    for (int idx = tid; idx < 45 * 56; idx += 512) {
        int k = idx / 56, dp = idx % 56;
        float a = (2 * dp     < 100) ? isft[(2 * dp) * 45 + k]     : 0.f;
        float b = (2 * dp + 1 < 100) ? isft[(2 * dp + 1) * 45 + k] : 0.f;
        bi2[idx] = pack2(a, b);
    }
    for (int idx = tid; idx < 100 * 24; idx += 512) {
        int d = idx / 24, cq = idx % 24;
        float a = (2 * cq     < 45) ? sft[(2 * cq) * 100 + d]     : 0.f;
        float b = (2 * cq + 1 < 45) ? sft[(2 * cq + 1) * 100 + d] : 0.f;
        bs2[idx] = pack2(a, b);
    }

    const int ROWLIM = BATCH * OO;
    const int NT = (ROWLIM + 191) / 192;

    // stage one 192-row tile: 192 rows x 12 x 16B chunks = full 48-float rows
    auto stage = [&](int tile, float* buf) {
        for (int idx = tid; idx < 192 * 12; idx += 512) {
            int r = idx / 12, part = idx % 12;
            int gr = tile * 192 + r;
            if (gr < ROWLIM) {
                int b = gr / OO, oo = gr % OO;
                const float* src = (OS == 0 || oo < O)
                    ? y    + ((size_t)b * O  + oo)       * 48 + part * 4
                    : skip + ((size_t)b * OS + (oo - O)) * 48 + part * 4;
                cp_async16(smem_u32(buf + r * 48 + part * 4), src);
            }
        }
        CP_COMMIT();
    };

    __syncthreads();            // bi2/bs2 ready
    stage(blockIdx.x, ys0);
    CP_WAIT0();
    __syncthreads();

    int p = 0;
    for (int tile = blockIdx.x; tile < NT; tile += gridDim.x) {
        float* yb = p ? ys1 : ys0;
        float* yn = p ? ys0 : ys1;
        int nxt = tile + gridDim.x;
        if (nxt < NT) stage(nxt, yn);

        // ---- GEMM1: t[r][d] = relu(sum_k y[r][k]*isft[d][k]); 3 rows x 7 d-pairs ----
        {
            u64 acc[3][7];
            #pragma unroll
            for (int j = 0; j < 3; j++)
                #pragma unroll
                for (int q = 0; q < 7; q++) acc[j][q] = 0ull;
            #pragma unroll 5
            for (int k = 0; k < 45; k++) {
                u64 av[3];
                #pragma unroll
                for (int j = 0; j < 3; j++) {
                    float v = yb[(r0 + j) * 48 + k];
                    av[j] = pack2(v, v);
                }
                #pragma unroll
                for (int q = 0; q < 7; q++) {
                    u64 bv = bi2[k * 56 + blk * 7 + q];
                    #pragma unroll
                    for (int j = 0; j < 3; j++) fma2(acc[j][q], av[j], bv);
                }
            }
            #pragma unroll
            for (int q = 0; q < 7; q++) {
                int dp = blk * 7 + q;
                if (dp < 50) {
                    int d = 2 * dp;
                    #pragma unroll
                    for (int j = 0; j < 3; j++) {
                        float lo, hi;
                        unpack2(acc[j][q], lo, hi);
                        *(u64*)(ts + (r0 + j) * 104 + d) =
                            pack2(fmaxf(lo, 0.f), fmaxf(hi, 0.f));
                    }
                }
            }
        }
        __syncthreads();

        // ---- GEMM2: o[r][c] = sum_d t[r][d]*sft[c][d]; 3 rows x 3 c-pairs ----
        {
            u64 acc2[3][3];
            #pragma unroll
            for (int j = 0; j < 3; j++)
                #pragma unroll
                for (int q = 0; q < 3; q++) acc2[j][q] = 0ull;
            #pragma unroll 5
            for (int k = 0; k < 100; k++) {
                u64 av[3];
                #pragma unroll
                for (int j = 0; j < 3; j++) {
                    float v = ts[(r0 + j) * 104 + k];
                    av[j] = pack2(v, v);
                }
                #pragma unroll
                for (int q = 0; q < 3; q++) {
                    u64 bv = bs2[k * 24 + blk * 3 + q];
                    #pragma unroll
                    for (int j = 0; j < 3; j++) fma2(acc2[j][q], av[j], bv);
                }
            }
            // write outs into yb (GEMM1 finished with it at the barrier above);
            // 24 c-pairs cover cols 0..47, pads zero via zero-padded bs2
            #pragma unroll
            for (int q = 0; q < 3; q++) {
                int c = 2 * (blk * 3 + q);
                #pragma unroll
                for (int j = 0; j < 3; j++) {
                    float lo, hi;
                    unpack2(acc2[j][q], lo, hi);
                    *(u64*)(yb + (r0 + j) * 48 + c) = pack2(lo, hi);
                }
            }
        }
        __syncthreads();

        // ---- coalesced float4 copy to gmem ----
        {
            size_t base = (size_t)tile * 192 * 48;
            for (int idx = tid; idx < 192 * 12; idx += 512) {
                int r = idx / 12;
                if (tile * 192 + r < ROWLIM)
                    *(float4*)(out + base + (size_t)idx * 4) =
                        *(const float4*)(yb + idx * 4);
            }
        }
        CP_WAIT0();
        __syncthreads();
        p ^= 1;
    }
}

__global__ void final_sconv(const float* __restrict__ d4,
                            const float* __restrict__ w9,
                            float* __restrict__ out)
{
    __shared__ float ws[80];
    int tid = threadIdx.x;
    if (tid < 80) {
        int lh = tid % 5;
        ws[tid] = w9[tid] * sqrtf(PI_F / (4.f * (float)lh + 1.f));
    }
    __syncthreads();
    int idx = blockIdx.x * blockDim.x + tid;
    if (idx >= BATCH * 45) return;
    int c = idx % 45;
    int b = idx / 45;
    int lh = lh_of(c);
    float acc = 0.f;
    #pragma unroll
    for (int i = 0; i < 16; i++)
        acc += d4[((size_t)b * 16 + i) * 48 + c] * ws[i * 5 + lh];
    out[idx] = acc;
}

template<int I, int O>
static void run_sconv(const float* in, const float* w, float* y)
{
    constexpr int OCTA = (O >= 64) ? 64 : O;
    constexpr int OGO  = OCTA / 8;
    constexpr int NB   = (OGO == 2) ? 8 : 4;
    dim3 grid(BATCH / NB, O / OCTA);
    sconv5<I, O><<<grid, 192>>>(in, w, y);
}

template<int OO, int O, int OS>
static void run_nonlin(const float* y, const float* skip,
                       const float* isft, const float* sft, float* out)
{
    auto kf = nonlin6<OO, O, OS>;
    cudaFuncSetAttribute(kf, cudaFuncAttributeMaxDynamicSharedMemorySize, NL6_SMEM);
    kf<<<148, 512, NL6_SMEM>>>(y, skip, isft, sft, out);
}

extern "C" void kernel_launch(void* const* d_in, const int* in_sizes, int n_in,
                              void* d_out, int out_size)
{
    const float* x    = (const float*)d_in[0];
    const float* sft  = (const float*)d_in[1];
    const float* isft = (const float*)d_in[2];
    const float* w[9];
    for (int k = 0; k < 9; k++) w[k] = (const float*)d_in[3 + k];
    float* out = (float*)d_out;

    float *x48, *yb, *e1, *e2, *e3, *e4, *d1, *d2, *d3, *d4;
    cudaGetSymbolAddress((void**)&x48, g_x48);
    cudaGetSymbolAddress((void**)&yb, g_yb);
    cudaGetSymbolAddress((void**)&e1, g_e1);
    cudaGetSymbolAddress((void**)&e2, g_e2);
    cudaGetSymbolAddress((void**)&e3, g_e3);
    cudaGetSymbolAddress((void**)&e4, g_e4);
    cudaGetSymbolAddress((void**)&d1, g_d1);
    cudaGetSymbolAddress((void**)&d2, g_d2);
    cudaGetSymbolAddress((void**)&d3, g_d3);
    cudaGetSymbolAddress((void**)&d4, g_d4);

    pad48<<<(BATCH * 4 * 48 + 255) / 256, 256>>>(x, x48);

    run_sconv<4, 16>(x48, w[0], yb);
    run_nonlin<16, 16, 0>(yb, yb, isft, sft, e1);

    run_sconv<16, 32>(e1, w[1], yb);
    run_nonlin<32, 32, 0>(yb, yb, isft, sft, e2);

    run_sconv<32, 64>(e2, w[2], yb);
    run_nonlin<64, 64, 0>(yb, yb, isft, sft, e3);

    run_sconv<64, 128>(e3, w[3], yb);
    run_nonlin<128, 128, 0>(yb, yb, isft, sft, e4);

    run_sconv<128, 64>(e4, w[4], yb);
    run_nonlin<128, 64, 64>(yb, e3, isft, sft, d1);

    run_sconv<128, 32>(d1, w[5], yb);
    run_nonlin<64, 32, 32>(yb, e2, isft, sft, d2);

    run_sconv<64, 16>(d2, w[6], yb);
    run_nonlin<32, 16, 16>(yb, e1, isft, sft, d3);

    run_sconv<32, 16>(d3, w[7], yb);
    run_nonlin<16, 16, 0>(yb, yb, isft, sft, d4);

    final_sconv<<<(BATCH * 45 + 255) / 256, 256>>>(d4, w[8], out);
}